// round 2
// baseline (speedup 1.0000x reference)
#include <cuda_runtime.h>
#include <cuda_bf16.h>

// MFVI constituency: B=16, S=128.
// One CTA per (b, i). The per-(b,i) pair-score tile M[j,k] = s_pair[b,i,j,k] * mask2o
// is loaded ONCE from HBM into registers (256 threads x 64 floats), then 3 MFVI
// iterations run entirely out of registers + a tiny smem p-vector.
// Rows with mask[b,i,j]==0 are never loaded from HBM (whole row of M is zero).
// mask arrives as int32 (harness dtype set is {f32, i32, bf16}).

#define S 128
#define PADB 132  // mask smem row stride (bytes): conflict-free for row AND column access

__device__ __forceinline__ float sigmoidf_(float x) {
    return 1.0f / (1.0f + __expf(-x));
}

__global__ __launch_bounds__(256, 2)
void mfvi_kernel(const float* __restrict__ s_span,
                 const float* __restrict__ s_pair,
                 const int* __restrict__ mask,
                 float* __restrict__ out)
{
    __shared__ unsigned char smask[S * PADB];     // mask[b] packed to bytes, ~16.9 KB
    __shared__ __align__(16) float p[S];          // sigmoid(q)
    __shared__ float q_s[S];
    __shared__ float ss[S];                       // s_span row
    __shared__ float part[S];                     // h=1 partial sums

    const int t  = threadIdx.x;      // 256 threads
    const int bi = blockIdx.x;       // 0..2047
    const int b  = bi >> 7;
    const int i  = bi & 127;
    const int j  = t & 127;          // output column this thread contributes to
    const int h  = t >> 7;           // which 64-wide k-half this thread owns

    // ---- Stage mask[b] (64 KB int32 -> 16 KB bytes) into padded smem ----
    {
        const int4* mg = reinterpret_cast<const int4*>(mask + (size_t)b * S * S);
        #pragma unroll
        for (int n = 0; n < 16; n++) {
            int idx = n * 256 + t;          // int4 index 0..4095
            int row = idx >> 5;             // 32 int4 per 128-int row
            int c4  = idx & 31;
            int4 v = __ldg(mg + idx);
            uchar4 u;
            u.x = (unsigned char)(v.x != 0);
            u.y = (unsigned char)(v.y != 0);
            u.z = (unsigned char)(v.z != 0);
            u.w = (unsigned char)(v.w != 0);
            *reinterpret_cast<uchar4*>(&smask[row * PADB + (c4 << 2)]) = u;
        }
    }
    if (t < S) {
        float v = s_span[(size_t)bi * S + t];
        ss[t]  = v;
        q_s[t] = v;
    }
    __syncthreads();

    // ---- Load masked M[j, kbase..kbase+63] into registers ----
    float Mreg[64];
    const unsigned char mij = smask[i * PADB + j];   // mask[b,i,j]
    const int lo = min(i, j);
    const int hi = max(i, j);
    const int kbase = h << 6;

    if (mij) {
        const float4* sp4 = reinterpret_cast<const float4*>(
            s_pair + ((size_t)bi * S + (size_t)j) * S + kbase);
        #pragma unroll
        for (int n = 0; n < 16; n++) {
            float4 v = __ldg(sp4 + n);
            int k0 = kbase + (n << 2);
            // span[b,j,k] = mask[b,j,k] | mask[b,k,j]
            uchar4 a4 = *reinterpret_cast<const uchar4*>(&smask[j * PADB + k0]);
            unsigned char b0 = smask[(k0 + 0) * PADB + j];
            unsigned char b1 = smask[(k0 + 1) * PADB + j];
            unsigned char b2 = smask[(k0 + 2) * PADB + j];
            unsigned char b3 = smask[(k0 + 3) * PADB + j];
            Mreg[4*n+0] = ((k0+0 != lo) && (k0+0 != hi) && ((a4.x | b0) != 0)) ? v.x : 0.0f;
            Mreg[4*n+1] = ((k0+1 != lo) && (k0+1 != hi) && ((a4.y | b1) != 0)) ? v.y : 0.0f;
            Mreg[4*n+2] = ((k0+2 != lo) && (k0+2 != hi) && ((a4.z | b2) != 0)) ? v.z : 0.0f;
            Mreg[4*n+3] = ((k0+3 != lo) && (k0+3 != hi) && ((a4.w | b3) != 0)) ? v.w : 0.0f;
        }
    } else {
        // whole row masked out: zero contribution, and the HBM loads are skipped
        #pragma unroll
        for (int n = 0; n < 64; n++) Mreg[n] = 0.0f;
    }

    // ---- 3 MFVI iterations, fully register/smem resident ----
    #pragma unroll
    for (int it = 0; it < 3; it++) {
        __syncthreads();
        if (t < S) p[t] = sigmoidf_(q_s[t]);
        __syncthreads();

        float acc = 0.0f;
        #pragma unroll
        for (int n = 0; n < 16; n++) {
            float4 pv = *reinterpret_cast<const float4*>(&p[kbase + (n << 2)]);  // broadcast
            acc = fmaf(pv.x, Mreg[4*n+0], acc);
            acc = fmaf(pv.y, Mreg[4*n+1], acc);
            acc = fmaf(pv.z, Mreg[4*n+2], acc);
            acc = fmaf(pv.w, Mreg[4*n+3], acc);
        }
        if (h == 1) part[j] = acc;
        __syncthreads();
        if (t < S) q_s[j] = ss[j] + acc + part[j];
    }

    __syncthreads();
    if (t < S) out[(size_t)bi * S + t] = sigmoidf_(q_s[t]);
}

extern "C" void kernel_launch(void* const* d_in, const int* in_sizes, int n_in,
                              void* d_out, int out_size) {
    const float* s_span = (const float*)d_in[0];
    const float* s_pair = (const float*)d_in[1];
    const int*   mask   = (const int*)d_in[2];
    float* out = (float*)d_out;

    mfvi_kernel<<<16 * 128, 256>>>(s_span, s_pair, mask, out);
}